// round 2
// baseline (speedup 1.0000x reference)
#include <cuda_runtime.h>
#include <cuda_bf16.h>
#include <math.h>

// Problem constants
#define B_SZ 512
#define K_SZ 32
#define D_SZ 768
#define N_SENSES 200000
#define NEG_INF -1e30f

// Scratch for per-sample NLL (deterministic 2-pass reduction, no float atomics)
__device__ float g_nll[B_SZ];

// Kernel 1: one CTA per sample. 32 warps, warp w computes logit for candidate w.
__global__ __launch_bounds__(1024, 1)
void cbert_logits_kernel(const float* __restrict__ reps,
                         const float* __restrict__ weight,
                         const float* __restrict__ bias,
                         const int* __restrict__ sense_ids,
                         const int* __restrict__ target_ids,
                         float* __restrict__ out, int out_size) {
    const int b = blockIdx.x;
    const int tid = threadIdx.x;
    const int wid = tid >> 5;   // warp id == candidate k
    const int lane = tid & 31;

    __shared__ float s_reps[D_SZ];        // 3 KB
    __shared__ float s_logits[K_SZ];

    // Stage reps[b] into smem: 768 floats = 192 float4
    {
        const float4* src = reinterpret_cast<const float4*>(reps + (size_t)b * D_SZ);
        float4* dst = reinterpret_cast<float4*>(s_reps);
        if (tid < D_SZ / 4) dst[tid] = src[tid];
    }
    __syncthreads();

    // Each warp: dot(weight[id], reps[b]) + bias[id], or NEG_INF if padded
    const int id = sense_ids[b * K_SZ + wid];
    float logit = NEG_INF;
    if (id >= 0 && id < N_SENSES) {
        const float4* wrow = reinterpret_cast<const float4*>(weight + (size_t)id * D_SZ);
        const float4* rrow = reinterpret_cast<const float4*>(s_reps);
        float acc = 0.f;
        // 192 float4 per row, 32 lanes -> 6 float4 per lane (MLP=6)
        #pragma unroll
        for (int j = 0; j < 6; ++j) {
            const int i = lane + 32 * j;
            float4 w4 = wrow[i];
            float4 r4 = rrow[i];
            acc = fmaf(w4.x, r4.x, acc);
            acc = fmaf(w4.y, r4.y, acc);
            acc = fmaf(w4.z, r4.z, acc);
            acc = fmaf(w4.w, r4.w, acc);
        }
        // warp reduce
        #pragma unroll
        for (int off = 16; off > 0; off >>= 1)
            acc += __shfl_down_sync(0xFFFFFFFFu, acc, off);
        if (lane == 0) logit = acc + bias[id];
    }
    if (lane == 0) s_logits[wid] = logit;
    __syncthreads();

    // Warp 0: masked softmax over 32 logits, NLL + argmax-correct
    if (wid == 0) {
        float v = s_logits[lane];

        // max + first-index argmax (prefer larger val; tie -> smaller idx)
        float mval = v; int midx = lane;
        #pragma unroll
        for (int off = 16; off > 0; off >>= 1) {
            float ov = __shfl_down_sync(0xFFFFFFFFu, mval, off);
            int   oi = __shfl_down_sync(0xFFFFFFFFu, midx, off);
            if (ov > mval || (ov == mval && oi < midx)) { mval = ov; midx = oi; }
        }
        mval = __shfl_sync(0xFFFFFFFFu, mval, 0);
        midx = __shfl_sync(0xFFFFFFFFu, midx, 0);

        // sum exp (padded entries: exp(NEG_INF - max) == 0)
        float e = expf(v - mval);
        #pragma unroll
        for (int off = 16; off > 0; off >>= 1)
            e += __shfl_down_sync(0xFFFFFFFFu, e, off);
        float sumexp = __shfl_sync(0xFFFFFFFFu, e, 0);

        const int tgt = target_ids[b];
        float tlogit = __shfl_sync(0xFFFFFFFFu, v, tgt & 31);

        if (lane == 0) {
            float nll = -(tlogit - mval - logf(sumexp));
            g_nll[b] = nll;
            if (1 + b < out_size) out[1 + b] = (midx == tgt) ? 1.0f : 0.0f;
        }
    }
}

// Kernel 2: deterministic sum of g_nll -> out[0] = mean
__global__ void cbert_reduce_kernel(float* __restrict__ out, int out_size) {
    __shared__ float s[B_SZ];
    const int tid = threadIdx.x;
    s[tid] = g_nll[tid];
    __syncthreads();
    for (int off = B_SZ / 2; off > 0; off >>= 1) {
        if (tid < off) s[tid] += s[tid + off];
        __syncthreads();
    }
    if (tid == 0 && out_size > 0) out[0] = s[0] / (float)B_SZ;
}

extern "C" void kernel_launch(void* const* d_in, const int* in_sizes, int n_in,
                              void* d_out, int out_size) {
    const float* reps = (const float*)d_in[0];
    const float* weight = (const float*)d_in[1];
    const float* bias = (const float*)d_in[2];
    const int* sense_ids = (const int*)d_in[3];
    const int* target_ids = (const int*)d_in[4];
    float* out = (float*)d_out;

    cbert_logits_kernel<<<B_SZ, 1024>>>(reps, weight, bias, sense_ids, target_ids, out, out_size);
    cbert_reduce_kernel<<<1, B_SZ>>>(out, out_size);
}